// round 3
// baseline (speedup 1.0000x reference)
#include <cuda_runtime.h>
#include <cuda_bf16.h>
#include <math.h>

// ---------------------------------------------------------------------------
// Problem constants (fixed shapes from setup_inputs)
// ---------------------------------------------------------------------------
#define NMAX   50000
#define EMAX   800000
#define ETMAX  (NMAX + EMAX)
#define F1     128     // heads(4) * out_c(32) of layer 1
#define H1     4
#define OC1    32
#define OC2    32

// ---------------------------------------------------------------------------
// Scratch (device globals; no allocation allowed)
// ---------------------------------------------------------------------------
__device__ __align__(16) float g_h1 [NMAX * F1];    // layer1 x@W1
__device__ __align__(16) float g_o1 [NMAX * F1];    // layer1 aggregated (then elu)
__device__ __align__(16) float g_h2 [NMAX * OC2];   // layer2 h
__device__ __align__(16) float g_es1[NMAX * H1];
__device__ __align__(16) float g_ed1[NMAX * H1];
__device__ __align__(16) float g_es2[NMAX];
__device__ __align__(16) float g_ed2[NMAX];
__device__ __align__(16) float g_ex1[ETMAX * H1];   // exp(score), layer1
__device__ __align__(16) float g_ex2[ETMAX];
__device__ __align__(16) float g_dn1[NMAX * H1];    // softmax denominators
__device__ __align__(16) float g_dn2[NMAX];
__device__ int g_src[ETMAX];
__device__ int g_dst[ETMAX];
__device__ int g_flag[1];

static inline int cdiv(int a, int b) { return (a + b - 1) / b; }

// ---------------------------------------------------------------------------
// Edge-index dtype detection: int64 little-endian values < 2^31 have all-zero
// high words. Check odd 32-bit words of the first 64 values.
// ---------------------------------------------------------------------------
__global__ void detect_dtype_kernel(const int* __restrict__ ei, int* flag) {
    if (threadIdx.x == 0 && blockIdx.x == 0) {
        int any = 0;
        #pragma unroll 4
        for (int k = 1; k < 128; k += 2) any |= ei[k];
        flag[0] = (any == 0) ? 1 : 0;
    }
}

// Normalize edge index into int32 src/dst; append self-loops.
__global__ void build_edges_kernel(const int* __restrict__ ei, int E, int n,
                                   int* __restrict__ src, int* __restrict__ dst,
                                   const int* __restrict__ flag) {
    int i = blockIdx.x * blockDim.x + threadIdx.x;
    int tot = E + n;
    if (i >= tot) return;
    if (i < E) {
        if (flag[0]) {
            const long long* p = (const long long*)ei;
            src[i] = (int)p[i];
            dst[i] = (int)p[(long long)E + i];
        } else {
            src[i] = ei[i];
            dst[i] = ei[E + i];
        }
    } else {
        int v = i - E;
        src[i] = v;
        dst[i] = v;
    }
}

// ---------------------------------------------------------------------------
// Tiled GEMM: H[n, OUT_COLS] = X[n, 128] @ W[128, OUT_COLS]
// 256 threads; each thread owns 4 nodes x 4 cols in registers.
// ---------------------------------------------------------------------------
template<int OUT_COLS>
__global__ void gemm_kernel(const float* __restrict__ X,
                            const float* __restrict__ W,
                            float* __restrict__ Hout, int n) {
    constexpr int K   = 128;
    constexpr int KC  = 32;
    constexpr int COL_T  = OUT_COLS / 4;       // 32 (L1) or 8 (L2)
    constexpr int ROW_T  = 256 / COL_T;        // 8 or 32
    constexpr int NPT    = 4;
    constexpr int TILE_N = ROW_T * NPT;        // 32 or 128

    __shared__ __align__(16) float sW[KC][OUT_COLS];
    __shared__ float sX[TILE_N][KC + 1];

    const int tid   = threadIdx.x;
    const int col_t = tid % COL_T;
    const int row_t = tid / COL_T;

    for (int base = blockIdx.x * TILE_N; base < n; base += gridDim.x * TILE_N) {
        float4 acc[NPT];
        #pragma unroll
        for (int j = 0; j < NPT; j++) acc[j] = make_float4(0.f, 0.f, 0.f, 0.f);

        for (int kc = 0; kc < K; kc += KC) {
            for (int i = tid; i < KC * OUT_COLS; i += 256) {
                int kk = i / OUT_COLS, cc = i % OUT_COLS;
                sW[kk][cc] = W[(kc + kk) * OUT_COLS + cc];
            }
            for (int i = tid; i < TILE_N * KC; i += 256) {
                int r = i / KC, kk = i % KC;
                int node = base + r;
                sX[r][kk] = (node < n) ? X[node * K + kc + kk] : 0.f;
            }
            __syncthreads();
            #pragma unroll
            for (int kk = 0; kk < KC; kk++) {
                float4 w = *(const float4*)&sW[kk][col_t * 4];
                #pragma unroll
                for (int j = 0; j < NPT; j++) {
                    float xv = sX[row_t * NPT + j][kk];
                    acc[j].x += xv * w.x; acc[j].y += xv * w.y;
                    acc[j].z += xv * w.z; acc[j].w += xv * w.w;
                }
            }
            __syncthreads();
        }
        #pragma unroll
        for (int j = 0; j < NPT; j++) {
            int node = base + row_t * NPT + j;
            if (node < n)
                *(float4*)&Hout[node * OUT_COLS + col_t * 4] = acc[j];
        }
    }
}

// ---------------------------------------------------------------------------
// Per-node attention logits: e_src[n,h] = <h[n,h,:], a_src[h,:]>, same for dst
// ---------------------------------------------------------------------------
template<int HEADS, int OC>
__global__ void node_logits_kernel(const float* __restrict__ Hm,
                                   const float* __restrict__ a_src,
                                   const float* __restrict__ a_dst,
                                   float* __restrict__ es,
                                   float* __restrict__ ed, int n) {
    int idx = blockIdx.x * blockDim.x + threadIdx.x;
    if (idx >= n * HEADS) return;
    int node = idx / HEADS, h = idx % HEADS;
    const float* hp = Hm + node * HEADS * OC + h * OC;
    float ss = 0.f, dd = 0.f;
    #pragma unroll
    for (int c = 0; c < OC; c++) {
        float v = hp[c];
        ss += v * a_src[h * OC + c];
        dd += v * a_dst[h * OC + c];
    }
    es[idx] = ss;
    ed[idx] = dd;
}

// ---------------------------------------------------------------------------
// Edge scores: ex = exp(leaky_relu(e_src[s]+e_dst[d])); accumulate denom[d].
// No max-subtraction: softmax ratio is invariant and scores are O(1).
// ---------------------------------------------------------------------------
template<int HEADS>
__global__ void edge_score_kernel(const int* __restrict__ src,
                                  const int* __restrict__ dst,
                                  const float* __restrict__ es,
                                  const float* __restrict__ ed,
                                  float* __restrict__ ex,
                                  float* __restrict__ den, int etot) {
    int i = blockIdx.x * blockDim.x + threadIdx.x;
    if (i >= etot) return;
    int s = src[i], d = dst[i];
    #pragma unroll
    for (int h = 0; h < HEADS; h++) {
        float v = es[s * HEADS + h] + ed[d * HEADS + h];
        v = v > 0.f ? v : 0.2f * v;
        float e = __expf(v);
        ex[i * HEADS + h] = e;
        atomicAdd(&den[d * HEADS + h], e);
    }
}

// ---------------------------------------------------------------------------
// Aggregation, 128-wide features (4 heads x 32): one warp per edge.
// Lane l handles 4 floats; head = l/8. float4 vector atomics (red.v4).
// ---------------------------------------------------------------------------
__global__ void agg128_kernel(const int* __restrict__ src,
                              const int* __restrict__ dst,
                              const float* __restrict__ Hm,
                              const float* __restrict__ ex,
                              const float* __restrict__ den,
                              float* __restrict__ out, int etot) {
    int warp = (blockIdx.x * blockDim.x + threadIdx.x) >> 5;
    int lane = threadIdx.x & 31;
    if (warp >= etot) return;
    int s = src[warp], d = dst[warp];
    int head = lane >> 3;
    float alpha = ex[warp * 4 + head] / den[d * 4 + head];
    float4 hv = *(const float4*)&Hm[s * 128 + lane * 4];
    float4 v = make_float4(hv.x * alpha, hv.y * alpha, hv.z * alpha, hv.w * alpha);
    atomicAdd((float4*)&out[d * 128 + lane * 4], v);
}

// Aggregation, 32-wide features (1 head): 8 lanes per edge, 4 edges/warp.
__global__ void agg32_kernel(const int* __restrict__ src,
                             const int* __restrict__ dst,
                             const float* __restrict__ Hm,
                             const float* __restrict__ ex,
                             const float* __restrict__ den,
                             float* __restrict__ out, int etot) {
    int t = blockIdx.x * blockDim.x + threadIdx.x;
    int e = t >> 3;
    int sub = t & 7;
    if (e >= etot) return;
    int s = src[e], d = dst[e];
    float alpha = ex[e] / den[d];
    float4 hv = *(const float4*)&Hm[s * 32 + sub * 4];
    float4 v = make_float4(hv.x * alpha, hv.y * alpha, hv.z * alpha, hv.w * alpha);
    atomicAdd((float4*)&out[d * 32 + sub * 4], v);
}

// ---------------------------------------------------------------------------
// Epilogues
// ---------------------------------------------------------------------------
__global__ void bias_elu_kernel(float* __restrict__ o,
                                const float* __restrict__ b, int total) {
    int idx = blockIdx.x * blockDim.x + threadIdx.x;
    if (idx >= total) return;
    float v = o[idx] + b[idx % F1];
    o[idx] = v > 0.f ? v : expm1f(v);
}

__global__ void bias_kernel(float* __restrict__ o,
                            const float* __restrict__ b, int total) {
    int idx = blockIdx.x * blockDim.x + threadIdx.x;
    if (idx >= total) return;
    o[idx] += b[idx % OC2];
}

// ---------------------------------------------------------------------------
// Launch
// ---------------------------------------------------------------------------
extern "C" void kernel_launch(void* const* d_in, const int* in_sizes, int n_in,
                              void* d_out, int out_size) {
    const float* x      = (const float*)d_in[0];
    const int*   ei     = (const int*)  d_in[1];
    const float* W1     = (const float*)d_in[2];
    const float* a_src1 = (const float*)d_in[3];
    const float* a_dst1 = (const float*)d_in[4];
    const float* b1     = (const float*)d_in[5];
    const float* W2     = (const float*)d_in[6];
    const float* a_src2 = (const float*)d_in[7];
    const float* a_dst2 = (const float*)d_in[8];
    const float* b2     = (const float*)d_in[9];
    float* out = (float*)d_out;

    int n = in_sizes[0] / 128;
    long long ee = in_sizes[1];
    int E = (int)(ee / 2);
    if (E > EMAX) E = (int)(ee / 4);   // harness counted int64 as 2x int32 words
    int ET = E + n;

    // Resolve scratch symbols
    float *h1, *o1, *h2, *es1, *ed1, *es2, *ed2, *ex1, *ex2, *dn1, *dn2;
    int *src, *dst, *flag;
    cudaGetSymbolAddress((void**)&h1,  g_h1);
    cudaGetSymbolAddress((void**)&o1,  g_o1);
    cudaGetSymbolAddress((void**)&h2,  g_h2);
    cudaGetSymbolAddress((void**)&es1, g_es1);
    cudaGetSymbolAddress((void**)&ed1, g_ed1);
    cudaGetSymbolAddress((void**)&es2, g_es2);
    cudaGetSymbolAddress((void**)&ed2, g_ed2);
    cudaGetSymbolAddress((void**)&ex1, g_ex1);
    cudaGetSymbolAddress((void**)&ex2, g_ex2);
    cudaGetSymbolAddress((void**)&dn1, g_dn1);
    cudaGetSymbolAddress((void**)&dn2, g_dn2);
    cudaGetSymbolAddress((void**)&src, g_src);
    cudaGetSymbolAddress((void**)&dst, g_dst);
    cudaGetSymbolAddress((void**)&flag, g_flag);

    // Edge list normalization
    detect_dtype_kernel<<<1, 32>>>(ei, flag);
    build_edges_kernel<<<cdiv(ET, 256), 256>>>(ei, E, n, src, dst, flag);

    // ---------------- Layer 1 ----------------
    gemm_kernel<F1><<<cdiv(n, 32), 256>>>(x, W1, h1, n);
    node_logits_kernel<H1, OC1><<<cdiv(n * H1, 256), 256>>>(h1, a_src1, a_dst1, es1, ed1, n);
    cudaMemsetAsync(dn1, 0, (size_t)n * H1 * sizeof(float));
    cudaMemsetAsync(o1,  0, (size_t)n * F1 * sizeof(float));
    edge_score_kernel<H1><<<cdiv(ET, 256), 256>>>(src, dst, es1, ed1, ex1, dn1, ET);
    agg128_kernel<<<cdiv(ET * 32, 256), 256>>>(src, dst, h1, ex1, dn1, o1, ET);
    bias_elu_kernel<<<cdiv(n * F1, 256), 256>>>(o1, b1, n * F1);

    // ---------------- Layer 2 ----------------
    gemm_kernel<OC2><<<cdiv(n, 128), 256>>>(o1, W2, h2, n);
    node_logits_kernel<1, OC2><<<cdiv(n, 256), 256>>>(h2, a_src2, a_dst2, es2, ed2, n);
    cudaMemsetAsync(dn2, 0, (size_t)n * sizeof(float));
    cudaMemsetAsync(out, 0, (size_t)n * OC2 * sizeof(float));
    edge_score_kernel<1><<<cdiv(ET, 256), 256>>>(src, dst, es2, ed2, ex2, dn2, ET);
    agg32_kernel<<<cdiv(ET * 8, 256), 256>>>(src, dst, h2, ex2, dn2, out, ET);
    bias_kernel<<<cdiv(n * OC2, 256), 256>>>(out, b2, n * OC2);
}

// round 4
// speedup vs baseline: 1.6848x; 1.6848x over previous
#include <cuda_runtime.h>
#include <cuda_bf16.h>
#include <math.h>

// ---------------------------------------------------------------------------
// Problem constants (fixed shapes from setup_inputs)
// ---------------------------------------------------------------------------
#define NMAX   50000
#define EMAX   800000
#define ETMAX  (NMAX + EMAX)
#define F1     128     // heads(4) * out_c(32) of layer 1
#define H1     4
#define OC1    32
#define OC2    32
#define SCAN_B 1024

// ---------------------------------------------------------------------------
// Scratch (device globals; no allocation allowed)
// ---------------------------------------------------------------------------
__device__ __align__(16) float g_h1 [NMAX * F1];    // layer1 x@W1
__device__ __align__(16) float g_o1 [NMAX * F1];    // layer1 out (post elu)
__device__ __align__(16) float g_h2 [NMAX * OC2];   // layer2 h
__device__ __align__(16) float g_es1[NMAX * H1];
__device__ __align__(16) float g_ed1[NMAX * H1];
__device__ __align__(16) float g_es2[NMAX];
__device__ __align__(16) float g_ed2[NMAX];
__device__ int g_src[ETMAX];
__device__ int g_dst[ETMAX];
__device__ int g_deg[NMAX];
__device__ int g_rowptr[NMAX + 1];
__device__ int g_cursor[NMAX];
__device__ int g_csr_src[ETMAX];
__device__ int g_blocksum[64];
__device__ int g_blockoff[64];
__device__ int g_flag[1];

static inline int cdiv(int a, int b) { return (a + b - 1) / b; }

// ---------------------------------------------------------------------------
// Edge-index dtype detection (int64 values < 2^31 -> zero high words)
// ---------------------------------------------------------------------------
__global__ void detect_dtype_kernel(const int* __restrict__ ei, int* flag) {
    if (threadIdx.x == 0 && blockIdx.x == 0) {
        int any = 0;
        #pragma unroll 4
        for (int k = 1; k < 128; k += 2) any |= ei[k];
        flag[0] = (any == 0) ? 1 : 0;
    }
}

// Normalize edge index to int32, append self-loops, histogram dst degrees.
__global__ void build_edges_kernel(const int* __restrict__ ei, int E, int n,
                                   int* __restrict__ src, int* __restrict__ dst,
                                   int* __restrict__ deg,
                                   const int* __restrict__ flag) {
    int i = blockIdx.x * blockDim.x + threadIdx.x;
    int tot = E + n;
    if (i >= tot) return;
    int s, d;
    if (i < E) {
        if (flag[0]) {
            const long long* p = (const long long*)ei;
            s = (int)p[i];
            d = (int)p[(long long)E + i];
        } else {
            s = ei[i];
            d = ei[E + i];
        }
    } else {
        s = i - E;
        d = i - E;
    }
    src[i] = s;
    dst[i] = d;
    atomicAdd(&deg[d], 1);
}

// ---------------------------------------------------------------------------
// 3-step exclusive scan of deg -> rowptr (n up to 64*1024)
// ---------------------------------------------------------------------------
__global__ void scan_block_kernel(const int* __restrict__ deg,
                                  int* __restrict__ rowptr,
                                  int* __restrict__ blocksum, int n) {
    __shared__ int sh[SCAN_B];
    int i = blockIdx.x * SCAN_B + threadIdx.x;
    int v = (i < n) ? deg[i] : 0;
    sh[threadIdx.x] = v;
    __syncthreads();
    for (int off = 1; off < SCAN_B; off <<= 1) {
        int t = (threadIdx.x >= off) ? sh[threadIdx.x - off] : 0;
        __syncthreads();
        sh[threadIdx.x] += t;
        __syncthreads();
    }
    if (i < n) rowptr[i + 1] = sh[threadIdx.x];   // inclusive, pre-offset
    if (threadIdx.x == SCAN_B - 1) blocksum[blockIdx.x] = sh[SCAN_B - 1];
}

__global__ void scan_partials_kernel(const int* __restrict__ blocksum,
                                     int* __restrict__ blockoff, int nb) {
    if (threadIdx.x == 0 && blockIdx.x == 0) {
        int run = 0;
        for (int b = 0; b < nb; b++) { blockoff[b] = run; run += blocksum[b]; }
    }
}

// Finalize rowptr (add block offsets) and init cursor = rowptr.
__global__ void finalize_rowptr_kernel(int* __restrict__ rowptr,
                                       int* __restrict__ cursor,
                                       const int* __restrict__ blockoff, int n) {
    int idx = blockIdx.x * blockDim.x + threadIdx.x;
    if (idx > n) return;
    int final_v;
    if (idx == 0) final_v = 0;
    else          final_v = rowptr[idx] + blockoff[(idx - 1) / SCAN_B];
    rowptr[idx] = final_v;
    if (idx < n) cursor[idx] = final_v;
}

__global__ void scatter_kernel(const int* __restrict__ src,
                               const int* __restrict__ dst,
                               int* __restrict__ cursor,
                               int* __restrict__ csr_src, int etot) {
    int i = blockIdx.x * blockDim.x + threadIdx.x;
    if (i >= etot) return;
    int p = atomicAdd(&cursor[dst[i]], 1);
    csr_src[p] = src[i];
}

// ---------------------------------------------------------------------------
// Tiled GEMM: H[n, OUT_COLS] = X[n, 128] @ W[128, OUT_COLS]
// ---------------------------------------------------------------------------
template<int OUT_COLS>
__global__ void gemm_kernel(const float* __restrict__ X,
                            const float* __restrict__ W,
                            float* __restrict__ Hout, int n) {
    constexpr int K   = 128;
    constexpr int KC  = 32;
    constexpr int COL_T  = OUT_COLS / 4;
    constexpr int ROW_T  = 256 / COL_T;
    constexpr int NPT    = 4;
    constexpr int TILE_N = ROW_T * NPT;

    __shared__ __align__(16) float sW[KC][OUT_COLS];
    __shared__ float sX[TILE_N][KC + 1];

    const int tid   = threadIdx.x;
    const int col_t = tid % COL_T;
    const int row_t = tid / COL_T;

    for (int base = blockIdx.x * TILE_N; base < n; base += gridDim.x * TILE_N) {
        float4 acc[NPT];
        #pragma unroll
        for (int j = 0; j < NPT; j++) acc[j] = make_float4(0.f, 0.f, 0.f, 0.f);

        for (int kc = 0; kc < K; kc += KC) {
            for (int i = tid; i < KC * OUT_COLS; i += 256) {
                int kk = i / OUT_COLS, cc = i % OUT_COLS;
                sW[kk][cc] = W[(kc + kk) * OUT_COLS + cc];
            }
            for (int i = tid; i < TILE_N * KC; i += 256) {
                int r = i / KC, kk = i % KC;
                int node = base + r;
                sX[r][kk] = (node < n) ? X[node * K + kc + kk] : 0.f;
            }
            __syncthreads();
            #pragma unroll
            for (int kk = 0; kk < KC; kk++) {
                float4 w = *(const float4*)&sW[kk][col_t * 4];
                #pragma unroll
                for (int j = 0; j < NPT; j++) {
                    float xv = sX[row_t * NPT + j][kk];
                    acc[j].x += xv * w.x; acc[j].y += xv * w.y;
                    acc[j].z += xv * w.z; acc[j].w += xv * w.w;
                }
            }
            __syncthreads();
        }
        #pragma unroll
        for (int j = 0; j < NPT; j++) {
            int node = base + row_t * NPT + j;
            if (node < n)
                *(float4*)&Hout[node * OUT_COLS + col_t * 4] = acc[j];
        }
    }
}

// ---------------------------------------------------------------------------
// Node logits, layer 1 (128-wide, 4 heads): one warp per node, coalesced
// float4 lane loads, 8-lane shuffle reductions per head.
// ---------------------------------------------------------------------------
__global__ void logits1_kernel(const float* __restrict__ Hm,
                               const float* __restrict__ a_src,
                               const float* __restrict__ a_dst,
                               float* __restrict__ es,
                               float* __restrict__ ed, int n) {
    int node = (blockIdx.x * blockDim.x + threadIdx.x) >> 5;
    if (node >= n) return;
    int lane = threadIdx.x & 31;
    int head = lane >> 3, sub = lane & 7;
    float4 hv = *(const float4*)&Hm[node * F1 + lane * 4];
    float4 as = *(const float4*)&a_src[head * OC1 + sub * 4];
    float4 ad = *(const float4*)&a_dst[head * OC1 + sub * 4];
    float ss = hv.x * as.x + hv.y * as.y + hv.z * as.z + hv.w * as.w;
    float dd = hv.x * ad.x + hv.y * ad.y + hv.z * ad.z + hv.w * ad.w;
    #pragma unroll
    for (int m = 1; m < 8; m <<= 1) {
        ss += __shfl_xor_sync(0xFFFFFFFF, ss, m);
        dd += __shfl_xor_sync(0xFFFFFFFF, dd, m);
    }
    if (sub == 0) {
        es[node * H1 + head] = ss;
        ed[node * H1 + head] = dd;
    }
}

// Node logits, layer 2 (32-wide, 1 head): warp per node, full reduction.
__global__ void logits2_kernel(const float* __restrict__ Hm,
                               const float* __restrict__ a_src,
                               const float* __restrict__ a_dst,
                               float* __restrict__ es,
                               float* __restrict__ ed, int n) {
    int node = (blockIdx.x * blockDim.x + threadIdx.x) >> 5;
    if (node >= n) return;
    int lane = threadIdx.x & 31;
    float h = Hm[node * OC2 + lane];
    float ss = h * a_src[lane];
    float dd = h * a_dst[lane];
    #pragma unroll
    for (int m = 1; m < 32; m <<= 1) {
        ss += __shfl_xor_sync(0xFFFFFFFF, ss, m);
        dd += __shfl_xor_sync(0xFFFFFFFF, dd, m);
    }
    if (lane == 0) { es[node] = ss; ed[node] = dd; }
}

// ---------------------------------------------------------------------------
// Fused layer-1 aggregation: warp per destination node.
// score + exp + denom + weighted sum + normalize + bias + ELU, no atomics.
// Lane owns 4 feature cols; head = lane/8.
// ---------------------------------------------------------------------------
__global__ void agg1_kernel(const int* __restrict__ rowptr,
                            const int* __restrict__ csr_src,
                            const float* __restrict__ Hm,
                            const float* __restrict__ es,
                            const float* __restrict__ ed,
                            const float* __restrict__ bias,
                            float* __restrict__ out, int n) {
    int d = (blockIdx.x * blockDim.x + threadIdx.x) >> 5;
    if (d >= n) return;
    int lane = threadIdx.x & 31;
    int head = lane >> 3;
    float edv = ed[d * H1 + head];
    float a0 = 0.f, a1 = 0.f, a2 = 0.f, a3 = 0.f, den = 0.f;
    int beg = rowptr[d], end = rowptr[d + 1];
    #pragma unroll 2
    for (int e = beg; e < end; e++) {
        int s = csr_src[e];
        float v = es[s * H1 + head] + edv;
        v = v > 0.f ? v : 0.2f * v;
        float ex = __expf(v);
        den += ex;
        float4 hv = *(const float4*)&Hm[s * F1 + lane * 4];
        a0 += hv.x * ex; a1 += hv.y * ex; a2 += hv.z * ex; a3 += hv.w * ex;
    }
    float inv = 1.0f / den;
    float4 bv = *(const float4*)&bias[lane * 4];
    float r0 = a0 * inv + bv.x;
    float r1 = a1 * inv + bv.y;
    float r2 = a2 * inv + bv.z;
    float r3 = a3 * inv + bv.w;
    // ELU
    r0 = r0 > 0.f ? r0 : expm1f(r0);
    r1 = r1 > 0.f ? r1 : expm1f(r1);
    r2 = r2 > 0.f ? r2 : expm1f(r2);
    r3 = r3 > 0.f ? r3 : expm1f(r3);
    *(float4*)&out[d * F1 + lane * 4] = make_float4(r0, r1, r2, r3);
}

// Fused layer-2 aggregation: warp per dst, lane owns 1 of 32 cols.
__global__ void agg2_kernel(const int* __restrict__ rowptr,
                            const int* __restrict__ csr_src,
                            const float* __restrict__ Hm,
                            const float* __restrict__ es,
                            const float* __restrict__ ed,
                            const float* __restrict__ bias,
                            float* __restrict__ out, int n) {
    int d = (blockIdx.x * blockDim.x + threadIdx.x) >> 5;
    if (d >= n) return;
    int lane = threadIdx.x & 31;
    float edv = ed[d];
    float acc = 0.f, den = 0.f;
    int beg = rowptr[d], end = rowptr[d + 1];
    #pragma unroll 2
    for (int e = beg; e < end; e++) {
        int s = csr_src[e];
        float v = es[s] + edv;
        v = v > 0.f ? v : 0.2f * v;
        float ex = __expf(v);
        den += ex;
        acc += Hm[s * OC2 + lane] * ex;
    }
    out[d * OC2 + lane] = acc / den + bias[lane];
}

// ---------------------------------------------------------------------------
// Launch
// ---------------------------------------------------------------------------
extern "C" void kernel_launch(void* const* d_in, const int* in_sizes, int n_in,
                              void* d_out, int out_size) {
    const float* x      = (const float*)d_in[0];
    const int*   ei     = (const int*)  d_in[1];
    const float* W1     = (const float*)d_in[2];
    const float* a_src1 = (const float*)d_in[3];
    const float* a_dst1 = (const float*)d_in[4];
    const float* b1     = (const float*)d_in[5];
    const float* W2     = (const float*)d_in[6];
    const float* a_src2 = (const float*)d_in[7];
    const float* a_dst2 = (const float*)d_in[8];
    const float* b2     = (const float*)d_in[9];
    float* out = (float*)d_out;

    int n = in_sizes[0] / 128;
    long long ee = in_sizes[1];
    int E = (int)(ee / 2);
    if (E > EMAX) E = (int)(ee / 4);   // int64 counted as 2x int32 words
    int ET = E + n;
    int nblk = cdiv(n, SCAN_B);

    float *h1, *o1, *h2, *es1, *ed1, *es2, *ed2;
    int *src, *dst, *deg, *rowptr, *cursor, *csr, *bsum, *boff, *flag;
    cudaGetSymbolAddress((void**)&h1,  g_h1);
    cudaGetSymbolAddress((void**)&o1,  g_o1);
    cudaGetSymbolAddress((void**)&h2,  g_h2);
    cudaGetSymbolAddress((void**)&es1, g_es1);
    cudaGetSymbolAddress((void**)&ed1, g_ed1);
    cudaGetSymbolAddress((void**)&es2, g_es2);
    cudaGetSymbolAddress((void**)&ed2, g_ed2);
    cudaGetSymbolAddress((void**)&src, g_src);
    cudaGetSymbolAddress((void**)&dst, g_dst);
    cudaGetSymbolAddress((void**)&deg, g_deg);
    cudaGetSymbolAddress((void**)&rowptr, g_rowptr);
    cudaGetSymbolAddress((void**)&cursor, g_cursor);
    cudaGetSymbolAddress((void**)&csr, g_csr_src);
    cudaGetSymbolAddress((void**)&bsum, g_blocksum);
    cudaGetSymbolAddress((void**)&boff, g_blockoff);
    cudaGetSymbolAddress((void**)&flag, g_flag);

    // -------- Graph preprocessing (CSR by dst, shared by both layers) -------
    detect_dtype_kernel<<<1, 32>>>(ei, flag);
    cudaMemsetAsync(deg, 0, (size_t)n * sizeof(int));
    build_edges_kernel<<<cdiv(ET, 256), 256>>>(ei, E, n, src, dst, deg, flag);
    scan_block_kernel<<<nblk, SCAN_B>>>(deg, rowptr, bsum, n);
    scan_partials_kernel<<<1, 32>>>(bsum, boff, nblk);
    finalize_rowptr_kernel<<<cdiv(n + 1, 256), 256>>>(rowptr, cursor, boff, n);
    scatter_kernel<<<cdiv(ET, 256), 256>>>(src, dst, cursor, csr, ET);

    // ---------------- Layer 1 ----------------
    gemm_kernel<F1><<<cdiv(n, 32), 256>>>(x, W1, h1, n);
    logits1_kernel<<<cdiv(n * 32, 256), 256>>>(h1, a_src1, a_dst1, es1, ed1, n);
    agg1_kernel<<<cdiv(n * 32, 256), 256>>>(rowptr, csr, h1, es1, ed1, b1, o1, n);

    // ---------------- Layer 2 ----------------
    gemm_kernel<OC2><<<cdiv(n, 128), 256>>>(o1, W2, h2, n);
    logits2_kernel<<<cdiv(n * 32, 256), 256>>>(h2, a_src2, a_dst2, es2, ed2, n);
    agg2_kernel<<<cdiv(n * 32, 256), 256>>>(rowptr, csr, h2, es2, ed2, b2, out, n);
}